// round 2
// baseline (speedup 1.0000x reference)
#include <cuda_runtime.h>
#include <math.h>

#define N_NODES 100000
#define N_EDGES 3200000
#define F_IN    128
#define HID     16
#define EMBD    100
#define NA      5
#define MLPH    128
#define SCAN_BLK 1024
#define NSCAN   ((N_NODES + SCAN_BLK - 1) / SCAN_BLK)   // 98

// ---------------- static device scratch (no runtime alloc allowed) ----------
__device__ int   g_counts[N_NODES];
__device__ int   g_offs[N_NODES + 1];
__device__ int   g_cursor[N_NODES];
__device__ int   g_bsums[128];
__device__ int   g_bbase[128];
__device__ int   g_srcs[N_EDGES];
__device__ float g_ws[N_EDGES];
__device__ float g_dinv[N_NODES];
__device__ float g_bufA[N_NODES * HID];
__device__ float g_bufB[N_NODES * HID];
__device__ float g_sink[4];

// ---------------- init: zero histogram + prefetch MLP weights into L2 -------
__global__ void k_init(const float* __restrict__ fcW1, const float* __restrict__ fcW2,
                       const float* __restrict__ W3, const float* __restrict__ fcW3) {
    int i = blockIdx.x * blockDim.x + threadIdx.x;
    if (i < N_NODES) g_counts[i] = 0;
    float v = 0.f;
    if (i < NA * EMBD * MLPH) v += fcW1[i];          // 64000
    if (i < MLPH * MLPH)      v += fcW2[i];          // 16384
    if (i < HID * EMBD)       v += W3[i];            // 1600
    if (i < MLPH * NA)        v += fcW3[i];          // 640
    if (v == 1.2345e37f) g_sink[0] = v;              // never true; defeats DCE
}

// ---------------- histogram of dst --------------------------------------
__global__ void k_hist(const int* __restrict__ dst, int E) {
    int i = blockIdx.x * blockDim.x + threadIdx.x;
    int e = i * 4;
    if (e + 3 < E) {
        int4 d = *(const int4*)(dst + e);
        atomicAdd(&g_counts[d.x], 1);
        atomicAdd(&g_counts[d.y], 1);
        atomicAdd(&g_counts[d.z], 1);
        atomicAdd(&g_counts[d.w], 1);
    } else {
        for (; e < E; ++e) atomicAdd(&g_counts[dst[e]], 1);
    }
}

// ---------------- exclusive scan (3 kernels) -----------------------------
__global__ void k_scanA() {
    __shared__ int s[SCAN_BLK];
    int t = threadIdx.x;
    int i = blockIdx.x * SCAN_BLK + t;
    int v = (i < N_NODES) ? g_counts[i] : 0;
    s[t] = v;
    __syncthreads();
    for (int off = 1; off < SCAN_BLK; off <<= 1) {
        int u = (t >= off) ? s[t - off] : 0;
        __syncthreads();
        s[t] += u;
        __syncthreads();
    }
    if (i < N_NODES) g_offs[i] = s[t] - v;               // local exclusive
    if (t == SCAN_BLK - 1) g_bsums[blockIdx.x] = s[t];   // block total
}

__global__ void k_scanB(int nb) {
    __shared__ int s[128];
    int t = threadIdx.x;
    int v = (t < nb) ? g_bsums[t] : 0;
    s[t] = v;
    __syncthreads();
    for (int off = 1; off < 128; off <<= 1) {
        int u = (t >= off) ? s[t - off] : 0;
        __syncthreads();
        s[t] += u;
        __syncthreads();
    }
    if (t < nb) g_bbase[t] = s[t] - v;
}

__global__ void k_scanC(int E) {
    int i = blockIdx.x * blockDim.x + threadIdx.x;
    if (i < N_NODES) {
        int o = g_offs[i] + g_bbase[i >> 10];
        g_offs[i] = o;
        g_cursor[i] = o;
    }
    if (i == 0) g_offs[N_NODES] = E;
}

// ---------------- scatter edges into CSR order ---------------------------
__global__ void k_scatter(const int* __restrict__ src, const int* __restrict__ dst,
                          const float* __restrict__ w, int E) {
    int i = blockIdx.x * blockDim.x + threadIdx.x;
    int e = i * 4;
    if (e + 3 < E) {
        int4 s4 = *(const int4*)(src + e);
        int4 d4 = *(const int4*)(dst + e);
        float4 w4 = *(const float4*)(w + e);
        int p;
        p = atomicAdd(&g_cursor[d4.x], 1); g_srcs[p] = s4.x; g_ws[p] = w4.x;
        p = atomicAdd(&g_cursor[d4.y], 1); g_srcs[p] = s4.y; g_ws[p] = w4.y;
        p = atomicAdd(&g_cursor[d4.z], 1); g_srcs[p] = s4.z; g_ws[p] = w4.z;
        p = atomicAdd(&g_cursor[d4.w], 1); g_srcs[p] = s4.w; g_ws[p] = w4.w;
    } else {
        for (; e < E; ++e) {
            int p = atomicAdd(&g_cursor[dst[e]], 1);
            g_srcs[p] = src[e]; g_ws[p] = w[e];
        }
    }
}

// ---------------- weighted degree -> dinv = rsqrt(1 + sum w) -------------
__global__ void k_dinv() {
    int warp = (blockIdx.x * blockDim.x + threadIdx.x) >> 5;
    int lane = threadIdx.x & 31;
    if (warp >= N_NODES) return;
    int beg = g_offs[warp], end = g_offs[warp + 1];
    float s = 0.f;
    for (int e = beg + lane; e < end; e += 32) s += g_ws[e];
    #pragma unroll
    for (int o = 16; o; o >>= 1) s += __shfl_xor_sync(0xffffffffu, s, o);
    if (lane == 0) {
        float deg = s + 1.0f;
        g_dinv[warp] = (deg > 0.f) ? rsqrtf(deg) : 0.f;
    }
}

// ---------------- gemm1: p1 = x @ W1  (128 -> 16), tiled -----------------
__global__ void k_gemm1(const float* __restrict__ x, const float* __restrict__ W1) {
    __shared__ __align__(16) float xs[64 * 132];
    __shared__ __align__(16) float ws[F_IN * HID];
    int t = threadIdx.x;
    int n0 = blockIdx.x * 64;

    // load W1 (2048 floats = 512 float4)
    for (int q = t; q < 512; q += 256)
        ((float4*)ws)[q] = ((const float4*)W1)[q];
    // load x tile [64][128] -> padded rows of 132
    #pragma unroll
    for (int it = 0; it < 8; ++it) {
        int q = t + it * 256;          // float4 index: n = q>>5, kq = q&31
        int n = q >> 5, kq = q & 31;
        float4 v = make_float4(0.f, 0.f, 0.f, 0.f);
        if (n0 + n < N_NODES)
            v = ((const float4*)x)[(size_t)(n0 + n) * 32 + kq];
        *(float4*)&xs[n * 132 + kq * 4] = v;
    }
    __syncthreads();

    int n = t >> 2, jg = t & 3;
    float4 acc = make_float4(0.f, 0.f, 0.f, 0.f);
    const float* xr = &xs[n * 132];
    #pragma unroll
    for (int kc = 0; kc < 32; ++kc) {
        float4 xv = *(const float4*)&xr[kc * 4];
        const float* wb = &ws[(kc * 4) * HID + jg * 4];
        float4 w0 = *(const float4*)(wb);
        float4 w1 = *(const float4*)(wb + HID);
        float4 w2 = *(const float4*)(wb + 2 * HID);
        float4 w3 = *(const float4*)(wb + 3 * HID);
        acc.x += xv.x * w0.x; acc.y += xv.x * w0.y; acc.z += xv.x * w0.z; acc.w += xv.x * w0.w;
        acc.x += xv.y * w1.x; acc.y += xv.y * w1.y; acc.z += xv.y * w1.z; acc.w += xv.y * w1.w;
        acc.x += xv.z * w2.x; acc.y += xv.z * w2.y; acc.z += xv.z * w2.z; acc.w += xv.z * w2.w;
        acc.x += xv.w * w3.x; acc.y += xv.w * w3.y; acc.z += xv.w * w3.z; acc.w += xv.w * w3.w;
    }
    if (n0 + n < N_NODES)
        ((float4*)g_bufA)[(size_t)(n0 + n) * 4 + jg] = acc;
}

// ---------------- agg: bufB = relu(A_norm @ bufA + bias) -----------------
// warp per node, 4 lanes per edge (float4 feature gather)
__global__ void k_agg(const float* __restrict__ bias) {
    int warp = (blockIdx.x * blockDim.x + threadIdx.x) >> 5;
    int lane = threadIdx.x & 31;
    if (warp >= N_NODES) return;
    int n = warp;
    int beg = g_offs[n], end = g_offs[n + 1];
    float dv = g_dinv[n];
    int g = lane >> 2, c = lane & 3;
    float4 acc = make_float4(0.f, 0.f, 0.f, 0.f);
    for (int e = beg + g; e < end; e += 8) {
        int s = g_srcs[e];
        float nrm = dv * g_ws[e] * g_dinv[s];
        float4 v = ((const float4*)g_bufA)[(size_t)s * 4 + c];
        acc.x += nrm * v.x; acc.y += nrm * v.y; acc.z += nrm * v.z; acc.w += nrm * v.w;
    }
    #pragma unroll
    for (int o = 16; o >= 4; o >>= 1) {
        acc.x += __shfl_xor_sync(0xffffffffu, acc.x, o);
        acc.y += __shfl_xor_sync(0xffffffffu, acc.y, o);
        acc.z += __shfl_xor_sync(0xffffffffu, acc.z, o);
        acc.w += __shfl_xor_sync(0xffffffffu, acc.w, o);
    }
    if (lane < 4) {
        float4 self = ((const float4*)g_bufA)[(size_t)n * 4 + lane];
        float4 b = ((const float4*)bias)[lane];
        float dv2 = dv * dv;
        float4 r;
        r.x = fmaxf(acc.x + dv2 * self.x + b.x, 0.f);
        r.y = fmaxf(acc.y + dv2 * self.y + b.y, 0.f);
        r.z = fmaxf(acc.z + dv2 * self.z + b.z, 0.f);
        r.w = fmaxf(acc.w + dv2 * self.w + b.w, 0.f);
        ((float4*)g_bufB)[(size_t)n * 4 + lane] = r;
    }
}

// ---------------- gemm16: bufA = bufB @ W (16 -> 16) ---------------------
__global__ void k_gemm16(const float* __restrict__ W) {
    __shared__ __align__(16) float ws[HID * HID];
    int t = threadIdx.x;
    if (t < 64) ((float4*)ws)[t] = ((const float4*)W)[t];
    __syncthreads();
    int n = blockIdx.x * blockDim.x + t;
    if (n >= N_NODES) return;
    const float4* row = (const float4*)(g_bufB + (size_t)n * HID);
    float4 x0 = row[0], x1 = row[1], x2 = row[2], x3 = row[3];
    float xv[16] = { x0.x, x0.y, x0.z, x0.w, x1.x, x1.y, x1.z, x1.w,
                     x2.x, x2.y, x2.z, x2.w, x3.x, x3.y, x3.z, x3.w };
    float4 a0 = make_float4(0.f,0.f,0.f,0.f), a1 = a0, a2 = a0, a3 = a0;
    #pragma unroll
    for (int i = 0; i < 16; ++i) {
        float xi = xv[i];
        const float4* wr = (const float4*)&ws[i * HID];
        float4 w0 = wr[0], w1 = wr[1], w2 = wr[2], w3 = wr[3];
        a0.x += xi * w0.x; a0.y += xi * w0.y; a0.z += xi * w0.z; a0.w += xi * w0.w;
        a1.x += xi * w1.x; a1.y += xi * w1.y; a1.z += xi * w1.z; a1.w += xi * w1.w;
        a2.x += xi * w2.x; a2.y += xi * w2.y; a2.z += xi * w2.z; a2.w += xi * w2.w;
        a3.x += xi * w3.x; a3.y += xi * w3.y; a3.z += xi * w3.z; a3.w += xi * w3.w;
    }
    float4* out = (float4*)(g_bufA + (size_t)n * HID);
    out[0] = a0; out[1] = a1; out[2] = a2; out[3] = a3;
}

// ---------------- final: layer-3 agg at pos (from bufB) + W3 + MLP -------
__global__ void k_final(const int* __restrict__ pos,
                        const float* __restrict__ W3, const float* __restrict__ b3,
                        const float* __restrict__ fcW1, const float* __restrict__ fcb1,
                        const float* __restrict__ fcW2, const float* __restrict__ fcb2,
                        const float* __restrict__ fcW3, const float* __restrict__ fcb3,
                        float* __restrict__ out) {
    __shared__ float agg3s[NA][HID];
    __shared__ int   s_pos[NA];
    __shared__ float zs[NA * EMBD];
    __shared__ float part[4][MLPH];
    __shared__ float h1s[MLPH];
    __shared__ float h2s[MLPH];

    int t = threadIdx.x, lane = t & 31, w = t >> 5;
    if (t < NA) s_pos[t] = pos[t];
    __syncthreads();

    if (w < NA) {
        int d_raw = s_pos[w];
        int d = (d_raw == -1) ? -1 : (d_raw < 0 ? 0 : d_raw);   // mimic clip
        int g = lane >> 2, c = lane & 3;
        float4 acc = make_float4(0.f, 0.f, 0.f, 0.f);
        float dv = 0.f;
        if (d >= 0) {
            dv = g_dinv[d];
            int beg = g_offs[d], end = g_offs[d + 1];
            for (int e = beg + g; e < end; e += 8) {
                int s = g_srcs[e];
                float nrm = dv * g_ws[e] * g_dinv[s];
                float4 v = ((const float4*)g_bufB)[(size_t)s * 4 + c];
                acc.x += nrm * v.x; acc.y += nrm * v.y;
                acc.z += nrm * v.z; acc.w += nrm * v.w;
            }
        }
        #pragma unroll
        for (int o = 16; o >= 4; o >>= 1) {
            acc.x += __shfl_xor_sync(0xffffffffu, acc.x, o);
            acc.y += __shfl_xor_sync(0xffffffffu, acc.y, o);
            acc.z += __shfl_xor_sync(0xffffffffu, acc.z, o);
            acc.w += __shfl_xor_sync(0xffffffffu, acc.w, o);
        }
        if (lane < 4) {
            float4 r = acc;
            if (d >= 0) {
                float4 self = ((const float4*)g_bufB)[(size_t)d * 4 + lane];
                float dv2 = dv * dv;
                r.x += dv2 * self.x; r.y += dv2 * self.y;
                r.z += dv2 * self.z; r.w += dv2 * self.w;
            }
            agg3s[w][lane * 4 + 0] = r.x;
            agg3s[w][lane * 4 + 1] = r.y;
            agg3s[w][lane * 4 + 2] = r.z;
            agg3s[w][lane * 4 + 3] = r.w;
        }
    }
    __syncthreads();

    // emb (500 values): z[a*100+j]
    if (t < NA * EMBD) {
        int a = t / EMBD, j = t - a * EMBD;
        float r;
        if (s_pos[a] == -1) {
            r = -1.0f;
        } else {
            r = b3[j];
            #pragma unroll
            for (int i = 0; i < HID; ++i) r += agg3s[a][i] * W3[i * EMBD + j];
        }
        zs[t] = r;
    }
    __syncthreads();

    // fc1: 500 -> 128, 4-way split over i
    {
        int o = t & 127, p = t >> 7;
        float s = 0.f;
        int i0 = p * 125;
        #pragma unroll 5
        for (int i = i0; i < i0 + 125; ++i) s += zs[i] * fcW1[i * MLPH + o];
        part[p][o] = s;
    }
    __syncthreads();
    if (t < MLPH) {
        float s = part[0][t] + part[1][t] + part[2][t] + part[3][t] + fcb1[t];
        h1s[t] = fmaxf(s, 0.f);
    }
    __syncthreads();
    if (t < MLPH) {
        float s = fcb2[t];
        #pragma unroll 8
        for (int i = 0; i < MLPH; ++i) s += h1s[i] * fcW2[i * MLPH + t];
        h2s[t] = fmaxf(s, 0.f);
    }
    __syncthreads();
    if (w < NA) {
        float s = 0.f;
        for (int i = lane; i < MLPH; i += 32) s += h2s[i] * fcW3[i * NA + w];
        #pragma unroll
        for (int o = 16; o; o >>= 1) s += __shfl_xor_sync(0xffffffffu, s, o);
        if (lane == 0) out[w] = s + fcb3[w];
    }
}

// ---------------- launch ---------------------------------------------------
extern "C" void kernel_launch(void* const* d_in, const int* in_sizes, int n_in,
                              void* d_out, int out_size) {
    const float* x    = (const float*)d_in[0];
    const int*   ei   = (const int*)d_in[1];
    const float* ew   = (const float*)d_in[2];
    const int*   pos  = (const int*)d_in[3];
    const float* W1   = (const float*)d_in[4];
    const float* b1   = (const float*)d_in[5];
    const float* W2   = (const float*)d_in[6];
    const float* b2   = (const float*)d_in[7];
    const float* W3   = (const float*)d_in[8];
    const float* b3   = (const float*)d_in[9];
    const float* fcW1 = (const float*)d_in[10];
    const float* fcb1 = (const float*)d_in[11];
    const float* fcW2 = (const float*)d_in[12];
    const float* fcb2 = (const float*)d_in[13];
    const float* fcW3 = (const float*)d_in[14];
    const float* fcb3 = (const float*)d_in[15];
    float* out = (float*)d_out;

    int E = in_sizes[2];                 // 3200000
    const int* src = ei;
    const int* dst = ei + E;

    int gridN  = (N_NODES + 255) / 256;          // 391
    int gridE4 = ((E + 3) / 4 + 255) / 256;      // 3125
    int gridW  = (N_NODES * 32 + 255) / 256;     // 12500 (warp per node)

    k_init<<<gridN, 256>>>(fcW1, fcW2, W3, fcW3);
    k_hist<<<gridE4, 256>>>(dst, E);
    k_scanA<<<NSCAN, SCAN_BLK>>>();
    k_scanB<<<1, 128>>>(NSCAN);
    k_scanC<<<gridN, 256>>>(E);
    k_scatter<<<gridE4, 256>>>(src, dst, ew, E);
    k_dinv<<<gridW, 256>>>();
    k_gemm1<<<(N_NODES + 63) / 64, 256>>>(x, W1);
    k_agg<<<gridW, 256>>>(b1);       // bufA(p1) -> bufB(out1)
    k_gemm16<<<gridN, 256>>>(W2);    // bufB -> bufA(p2)
    k_agg<<<gridW, 256>>>(b2);       // bufA(p2) -> bufB(out2)
    k_final<<<1, 512>>>(pos, W3, b3, fcW1, fcb1, fcW2, fcb2, fcW3, fcb3, out);
}